// round 3
// baseline (speedup 1.0000x reference)
#include <cuda_runtime.h>
#include <cstdint>

#define N_   16
#define C_   256
#define CM_  64
#define H_   96
#define W_   96
#define HW_  9216   // 96*96
#define NBLK_ 72    // conv1 blocks per image (HW/128)

// ---------------- scratch (device globals; no allocations) ----------------
__device__ float g_psum[N_ * NBLK_ * C_];       // conv1 per-block channel partial sums
__device__ float g_wdyn[N_ * CM_ * 25];
__device__ float g_watr[N_ * CM_ * 9];
__device__ float g_f  [N_ * CM_ * HW_];

// ---------------- tf32 helpers ----------------
__device__ __forceinline__ float f2tf(float f) {
    uint32_t r;
    asm("cvt.rna.tf32.f32 %0, %1;" : "=r"(r) : "f"(f));
    return __uint_as_float(r);
}

__device__ __forceinline__ void mma8(float* d, const uint32_t* a, uint32_t b0, uint32_t b1) {
    asm volatile(
        "mma.sync.aligned.m16n8k8.row.col.f32.tf32.tf32.f32 "
        "{%0,%1,%2,%3},{%4,%5,%6,%7},{%8,%9},{%0,%1,%2,%3};\n"
        : "+f"(d[0]), "+f"(d[1]), "+f"(d[2]), "+f"(d[3])
        : "r"(a[0]), "r"(a[1]), "r"(a[2]), "r"(a[3]), "r"(b0), "r"(b1));
}

// ---------------- kernel 1: 1x1 conv via tf32 mma + channel partial sums ----------------
// Block tile: 128 px (M) x 64 outs (N), K=256 in slabs of 32.
__global__ __launch_bounds__(256) void conv1_mma(
    const float* __restrict__ x,
    const float* __restrict__ conv_w,
    const float* __restrict__ conv_b)
{
    __shared__ float sm[8448];
    float* xs = sm;              // [32][136]  A: xs[k][px]
    float* wt = sm + 32 * 136;   // [32][72]   B: wt[k][o]
    int t = threadIdx.x, lane = t & 31, warp = t >> 5;
    int gq = lane >> 2, gr = lane & 3;
    int n = blockIdx.y;
    int blk = blockIdx.x;
    int base = blk * 128;
    int wm = warp & 3, wn = warp >> 2;
    const float* xp = x + (size_t)n * C_ * HW_ + base;
    float* psp = g_psum + ((size_t)n * NBLK_ + blk) * C_;

    float acc[2][4][4];
    #pragma unroll
    for (int a = 0; a < 2; a++)
        #pragma unroll
        for (int b = 0; b < 4; b++)
            #pragma unroll
            for (int c = 0; c < 4; c++) acc[a][b][c] = 0.f;

    int prow = t >> 3, pseg = t & 7;   // psum mapping: 32 rows x 8 segments

    for (int slab = 0; slab < 8; ++slab) {
        #pragma unroll
        for (int i = 0; i < 4; ++i) {
            int idx = t + i * 256;
            int r = idx >> 5, c4 = idx & 31;
            float4 v = *(const float4*)(xp + (size_t)(slab * 32 + r) * HW_ + c4 * 4);
            float4 w;
            w.x = f2tf(v.x); w.y = f2tf(v.y); w.z = f2tf(v.z); w.w = f2tf(v.w);
            *(float4*)(xs + r * 136 + c4 * 4) = w;
        }
        #pragma unroll
        for (int i = 0; i < 8; ++i) {
            int idx = t + i * 256;
            int k = idx & 31, o = idx >> 5;
            wt[k * 72 + o] = f2tf(conv_w[o * C_ + slab * 32 + k]);
        }
        __syncthreads();

        // channel partial sums for the global mean (deterministic)
        {
            float s = 0.f;
            #pragma unroll
            for (int i = 0; i < 16; ++i) s += xs[prow * 136 + pseg * 16 + i];
            s += __shfl_down_sync(0xffffffffu, s, 4, 8);
            s += __shfl_down_sync(0xffffffffu, s, 2, 8);
            s += __shfl_down_sync(0xffffffffu, s, 1, 8);
            if (pseg == 0) psp[slab * 32 + prow] = s;
        }

        #pragma unroll
        for (int kk = 0; kk < 4; ++kk) {
            int k0 = kk * 8;
            uint32_t a[2][4];
            #pragma unroll
            for (int mt = 0; mt < 2; ++mt) {
                int px = wm * 32 + mt * 16 + gq;
                a[mt][0] = __float_as_uint(xs[(k0 + gr) * 136 + px]);
                a[mt][1] = __float_as_uint(xs[(k0 + gr) * 136 + px + 8]);
                a[mt][2] = __float_as_uint(xs[(k0 + gr + 4) * 136 + px]);
                a[mt][3] = __float_as_uint(xs[(k0 + gr + 4) * 136 + px + 8]);
            }
            #pragma unroll
            for (int nt = 0; nt < 4; ++nt) {
                int o = wn * 32 + nt * 8 + gq;
                uint32_t b0 = __float_as_uint(wt[(k0 + gr) * 72 + o]);
                uint32_t b1 = __float_as_uint(wt[(k0 + gr + 4) * 72 + o]);
                mma8(acc[0][nt], a[0], b0, b1);
                mma8(acc[1][nt], a[1], b0, b1);
            }
        }
        __syncthreads();
    }

    float* st = sm + warp * 1056;  // 32*33 staging
    #pragma unroll
    for (int mt = 0; mt < 2; ++mt)
        #pragma unroll
        for (int nt = 0; nt < 4; ++nt) {
            int pr = mt * 16 + gq, oc = nt * 8 + 2 * gr;
            st[pr * 33 + oc]           = acc[mt][nt][0];
            st[pr * 33 + oc + 1]       = acc[mt][nt][1];
            st[(pr + 8) * 33 + oc]     = acc[mt][nt][2];
            st[(pr + 8) * 33 + oc + 1] = acc[mt][nt][3];
        }
    __syncwarp();
    float* fp = g_f + (size_t)n * CM_ * HW_ + base + wm * 32;
    #pragma unroll
    for (int ol = 0; ol < 32; ++ol) {
        int o = wn * 32 + ol;
        float v = st[lane * 33 + ol] + conv_b[o];
        fp[(size_t)o * HW_ + lane] = fmaxf(v, 0.f);
    }
}

// ---------------- kernel 2: finish mean + g + dynamic depthwise weights ----------------
__global__ __launch_bounds__(256) void weights_kernel(
    const float* __restrict__ conv_w, const float* __restrict__ conv_b,
    const float* __restrict__ ckw,  const float* __restrict__ ckb,
    const float* __restrict__ ck2w, const float* __restrict__ ck2b,
    const float* __restrict__ kw,   const float* __restrict__ kb,
    const float* __restrict__ k2w,  const float* __restrict__ k2b)
{
    __shared__ float sm[C_];
    int n = blockIdx.x;
    int t = threadIdx.x;
    {
        const float* pp = g_psum + (size_t)n * NBLK_ * C_ + t;
        float s = 0.f;
        #pragma unroll 8
        for (int b = 0; b < NBLK_; ++b) s += pp[(size_t)b * C_];
        sm[t] = s * (1.0f / (float)HW_);
    }
    __syncthreads();
    int warp = t >> 5, lane = t & 31;
    float a1 = ckw[0],  b1 = ckb[0];
    float a2 = ck2w[0], b2 = ck2b[0];
    for (int c = warp; c < CM_; c += 8) {
        float s = 0.f;
        #pragma unroll
        for (int kk = 0; kk < 8; kk++)
            s += sm[lane + kk * 32] * conv_w[c * C_ + lane + kk * 32];
        #pragma unroll
        for (int o = 16; o > 0; o >>= 1) s += __shfl_xor_sync(0xffffffffu, s, o);
        float g = fmaxf(s + conv_b[c], 0.f);
        int idx = n * CM_ + c;
        if (lane < 25) g_wdyn[idx * 25 + lane] = fmaf(a1, fmaf(g, kw[lane],  kb[lane]),  b1);
        if (lane < 9)  g_watr[idx * 9  + lane] = fmaf(a2, fmaf(g, k2w[lane], k2b[lane]), b2);
    }
}

// ---------------- kernel 3: fused depthwise + fuse GEMM ----------------
// Grid: (48 row-pair tiles, N, 2 branches). Block 512 threads (16 warps).
// Block tile: 192 px (2 rows) x 128 outs, K=64 in slabs of 16 channels.
// Warp: wm=warp&3 -> 48-px strip (3 m16), wn=warp>>2 -> 32 outs (4 n8).
// smem (floats): fh[16][6][104] | dwt[16][200] | wt[16][136] | wd[16][25] | wb[16]
#define FH_OFF   0
#define DWT_OFF  9984
#define WT_OFF   13184
#define WD_OFF   15360
#define WB_OFF   15760
#define DWF_SMEM_FLOATS 15776

__global__ __launch_bounds__(512) void dwfuse_kernel(
    float* __restrict__ out,
    const float* __restrict__ fuse_w,
    const float* __restrict__ fuse_b,
    const float* __restrict__ adap_b,
    const float* __restrict__ atrous_b)
{
    extern __shared__ float sm[];
    float* fh  = sm + FH_OFF;    // [c][r][col] stride 104, 6 rows
    float* dwt = sm + DWT_OFF;   // [k][px] stride 200
    float* wt  = sm + WT_OFF;    // [k][o]  stride 136
    float* wd  = sm + WD_OFF;    // dyn weights slab
    float* wb  = sm + WB_OFF;    // per-channel dw bias

    int t = threadIdx.x, lane = t & 31, warp = t >> 5;
    int gq = lane >> 2, gr = lane & 3;
    int tile = blockIdx.x;       // 0..47 (row pair)
    int n = blockIdx.y;
    int br = blockIdx.z;
    int row0 = tile * 2;
    int wm = warp & 3, wn = warp >> 2;
    const float* fbase = g_f + (size_t)n * CM_ * HW_;
    const float* dbias = br ? atrous_b : adap_b;

    float acc[3][4][4];
    #pragma unroll
    for (int a = 0; a < 3; a++)
        #pragma unroll
        for (int b = 0; b < 4; b++)
            #pragma unroll
            for (int c = 0; c < 4; c++) acc[a][b][c] = 0.f;

    for (int slab = 0; slab < 4; ++slab) {
        int cbase = slab * 16;
        // ---- load f halo: 16 ch x 6 rows x 100 cols (zero-padded) ----
        for (int idx = t; idx < 9600; idx += 512) {
            int c = idx / 600;
            int rem = idx - c * 600;
            int r = rem / 100;
            int j = rem - r * 100;
            int grow = row0 - 2 + r, gcol = j - 2;
            float v = 0.f;
            if (grow >= 0 && grow < H_ && gcol >= 0 && gcol < W_)
                v = fbase[(size_t)(cbase + c) * HW_ + grow * W_ + gcol];
            fh[c * 624 + r * 104 + j] = v;
        }
        // ---- load fuse_w slab + dyn weights + bias ----
        for (int idx = t; idx < 16 * 128; idx += 512) {
            int k = idx & 15, o = idx >> 4;
            wt[k * 136 + o] = f2tf(fuse_w[o * 64 + cbase + k]);
        }
        if (br == 0) {
            for (int idx = t; idx < 16 * 25; idx += 512)
                wd[idx] = g_wdyn[((size_t)n * CM_ + cbase) * 25 + idx];
        } else {
            if (t < 16 * 9)
                wd[t] = g_watr[((size_t)n * CM_ + cbase) * 9 + t];
        }
        if (t < 16) wb[t] = dbias[cbase + t];
        __syncthreads();

        // ---- compute dw tile: 16 ch x 192 px (4-px horizontal strips) ----
        for (int idx = t; idx < 768; idx += 512) {
            int c = idx / 48;
            int rem = idx - c * 48;
            int r = rem / 24;             // 0..1 output row within pair
            int j0 = (rem - r * 24) * 4;  // output col base
            const float* fhc = fh + c * 624 + r * 104;  // halo rows r..r+4
            float bias = wb[c];
            float o0, o1, o2, o3;
            if (br == 0) {
                const float* w5 = wd + c * 25;
                float s[5][8];
                #pragma unroll
                for (int i = 0; i < 5; ++i) {
                    float4 v0 = *(const float4*)(fhc + i * 104 + j0);
                    float4 v1 = *(const float4*)(fhc + i * 104 + j0 + 4);
                    s[i][0]=v0.x; s[i][1]=v0.y; s[i][2]=v0.z; s[i][3]=v0.w;
                    s[i][4]=v1.x; s[i][5]=v1.y; s[i][6]=v1.z; s[i][7]=v1.w;
                }
                float a0=bias, a1=bias, a2=bias, a3=bias;
                #pragma unroll
                for (int i = 0; i < 5; ++i)
                    #pragma unroll
                    for (int q = 0; q < 5; ++q) {
                        float w = w5[i * 5 + q];
                        a0 = fmaf(w, s[i][q],     a0);
                        a1 = fmaf(w, s[i][q + 1], a1);
                        a2 = fmaf(w, s[i][q + 2], a2);
                        a3 = fmaf(w, s[i][q + 3], a3);
                    }
                o0=a0; o1=a1; o2=a2; o3=a3;
            } else {
                const float* w3 = wd + c * 9;
                float s[3][8];
                #pragma unroll
                for (int i = 0; i < 3; ++i) {
                    float4 v0 = *(const float4*)(fhc + (2 * i) * 104 + j0);
                    float4 v1 = *(const float4*)(fhc + (2 * i) * 104 + j0 + 4);
                    s[i][0]=v0.x; s[i][1]=v0.y; s[i][2]=v0.z; s[i][3]=v0.w;
                    s[i][4]=v1.x; s[i][5]=v1.y; s[i][6]=v1.z; s[i][7]=v1.w;
                }
                float a0=bias, a1=bias, a2=bias, a3=bias;
                #pragma unroll
                for (int i = 0; i < 3; ++i)
                    #pragma unroll
                    for (int q = 0; q < 3; ++q) {
                        float w = w3[i * 3 + q];
                        a0 = fmaf(w, s[i][2 * q],     a0);
                        a1 = fmaf(w, s[i][2 * q + 1], a1);
                        a2 = fmaf(w, s[i][2 * q + 2], a2);
                        a3 = fmaf(w, s[i][2 * q + 3], a3);
                    }
                o0=a0; o1=a1; o2=a2; o3=a3;
            }
            float* dp = dwt + c * 200 + r * 96 + j0;
            dp[0] = f2tf(o0); dp[1] = f2tf(o1); dp[2] = f2tf(o2); dp[3] = f2tf(o3);
        }
        __syncthreads();

        // ---- mma: K slab of 16 = 2 k8 groups ----
        #pragma unroll
        for (int kk = 0; kk < 2; ++kk) {
            int k0 = kk * 8;
            uint32_t a[3][4];
            #pragma unroll
            for (int mt = 0; mt < 3; ++mt) {
                int px = wm * 48 + mt * 16 + gq;
                a[mt][0] = __float_as_uint(dwt[(k0 + gr) * 200 + px]);
                a[mt][1] = __float_as_uint(dwt[(k0 + gr) * 200 + px + 8]);
                a[mt][2] = __float_as_uint(dwt[(k0 + gr + 4) * 200 + px]);
                a[mt][3] = __float_as_uint(dwt[(k0 + gr + 4) * 200 + px + 8]);
            }
            #pragma unroll
            for (int nt = 0; nt < 4; ++nt) {
                int o = wn * 32 + nt * 8 + gq;
                uint32_t b0 = __float_as_uint(wt[(k0 + gr) * 136 + o]);
                uint32_t b1 = __float_as_uint(wt[(k0 + gr + 4) * 136 + o]);
                mma8(acc[0][nt], a[0], b0, b1);
                mma8(acc[1][nt], a[1], b0, b1);
                mma8(acc[2][nt], a[2], b0, b1);
            }
        }
        __syncthreads();
    }

    // ---- epilogue: per-warp staging (overlays fh region), per m-tile ----
    float* st = sm + warp * 528;   // [16][33]
    int obase = wn * 32;
    float* yp = out + ((size_t)n * 256 + (size_t)br * 128 + obase) * HW_
                + (size_t)row0 * W_ + wm * 48;
    #pragma unroll
    for (int mt = 0; mt < 3; ++mt) {
        __syncwarp();
        #pragma unroll
        for (int nt = 0; nt < 4; ++nt) {
            int oc = nt * 8 + 2 * gr;
            st[gq * 33 + oc]           = acc[mt][nt][0];
            st[gq * 33 + oc + 1]       = acc[mt][nt][1];
            st[(gq + 8) * 33 + oc]     = acc[mt][nt][2];
            st[(gq + 8) * 33 + oc + 1] = acc[mt][nt][3];
        }
        __syncwarp();
        #pragma unroll
        for (int it = 0; it < 16; ++it) {
            int o  = it * 2 + (lane >> 4);
            int px = lane & 15;
            float v = st[px * 33 + o] + fuse_b[obase + o];
            yp[(size_t)o * HW_ + mt * 16 + px] = v;
        }
    }
}

// ---------------- launcher ----------------
extern "C" void kernel_launch(void* const* d_in, const int* in_sizes, int n_in,
                              void* d_out, int out_size) {
    const float* x        = (const float*)d_in[0];
    const float* conv_w   = (const float*)d_in[1];
    const float* conv_b   = (const float*)d_in[2];
    const float* ckw      = (const float*)d_in[3];
    const float* ckb      = (const float*)d_in[4];
    const float* ck2w     = (const float*)d_in[5];
    const float* ck2b     = (const float*)d_in[6];
    const float* kw       = (const float*)d_in[7];
    const float* kb       = (const float*)d_in[8];
    const float* k2w      = (const float*)d_in[9];
    const float* k2b      = (const float*)d_in[10];
    const float* fuse_w   = (const float*)d_in[11];
    const float* fuse_b   = (const float*)d_in[12];
    const float* adap_b   = (const float*)d_in[13];
    const float* atrous_b = (const float*)d_in[14];
    float* out = (float*)d_out;

    cudaFuncSetAttribute(dwfuse_kernel, cudaFuncAttributeMaxDynamicSharedMemorySize,
                         DWF_SMEM_FLOATS * 4);

    conv1_mma<<<dim3(NBLK_, N_), 256>>>(x, conv_w, conv_b);
    weights_kernel<<<N_, 256>>>(conv_w, conv_b, ckw, ckb, ck2w, ck2b, kw, kb, k2w, k2b);
    dwfuse_kernel<<<dim3(H_ / 2, N_, 2), 512, DWF_SMEM_FLOATS * 4>>>(
        out, fuse_w, fuse_b, adap_b, atrous_b);
}

// round 4
// speedup vs baseline: 2.1957x; 2.1957x over previous
#include <cuda_runtime.h>
#include <cstdint>

#define N_   16
#define C_   256
#define CM_  64
#define H_   96
#define W_   96
#define HW_  9216   // 96*96
#define NBLK_ 72    // conv1 blocks per image (HW/128)

// ---------------- scratch (device globals; no allocations) ----------------
__device__ float g_psum[N_ * NBLK_ * C_];       // conv1 per-block channel partial sums
__device__ float g_wdyn[N_ * CM_ * 25];
__device__ float g_watr[N_ * CM_ * 9];
__device__ float g_f  [N_ * CM_ * HW_];
__device__ float g_dw0[N_ * CM_ * HW_];
__device__ float g_dw1[N_ * CM_ * HW_];

// ---------------- helpers ----------------
__device__ __forceinline__ float f2tf(float f) {
    uint32_t r;
    asm("cvt.rna.tf32.f32 %0, %1;" : "=r"(r) : "f"(f));
    return __uint_as_float(r);
}

__device__ __forceinline__ void mma8(float* d, const uint32_t* a, uint32_t b0, uint32_t b1) {
    asm volatile(
        "mma.sync.aligned.m16n8k8.row.col.f32.tf32.tf32.f32 "
        "{%0,%1,%2,%3},{%4,%5,%6,%7},{%8,%9},{%0,%1,%2,%3};\n"
        : "+f"(d[0]), "+f"(d[1]), "+f"(d[2]), "+f"(d[3])
        : "r"(a[0]), "r"(a[1]), "r"(a[2]), "r"(a[3]), "r"(b0), "r"(b1));
}

__device__ __forceinline__ uint32_t smem_u32(const void* p) {
    return (uint32_t)__cvta_generic_to_shared(p);
}
__device__ __forceinline__ void cp16(uint32_t dst, const void* src) {
    asm volatile("cp.async.cg.shared.global [%0], [%1], 16;" :: "r"(dst), "l"(src));
}
#define CP_COMMIT() asm volatile("cp.async.commit_group;")
#define CP_WAIT(n)  asm volatile("cp.async.wait_group %0;" :: "n"(n))

// ---------------- kernel 1: 1x1 conv via tf32 mma, cp.async double-buffered ----------------
// Block tile: 128 px (M) x 64 outs (N), K=256 in slabs of 32.
// smem layout (floats): xs[2][32][132] @0 (8448), wt[2][64][36] @8448 (4608)
__global__ __launch_bounds__(256) void conv1_mma(
    const float* __restrict__ x,
    const float* __restrict__ conv_w,
    const float* __restrict__ conv_b)
{
    extern __shared__ float sm[];
    float* xsb0 = sm;
    float* xsb1 = sm + 4224;
    float* wtb0 = sm + 8448;
    float* wtb1 = sm + 8448 + 2304;

    int t = threadIdx.x, lane = t & 31, warp = t >> 5;
    int gq = lane >> 2, gr = lane & 3;
    int n = blockIdx.y;
    int blk = blockIdx.x;
    int base = blk * 128;
    int wm = warp & 3, wn = warp >> 2;
    const float* xp = x + (size_t)n * C_ * HW_ + base;
    float* psp = g_psum + ((size_t)n * NBLK_ + blk) * C_;

    float acc[2][4][4];
    #pragma unroll
    for (int a = 0; a < 2; a++)
        #pragma unroll
        for (int b = 0; b < 4; b++)
            #pragma unroll
            for (int c = 0; c < 4; c++) acc[a][b][c] = 0.f;

    int prow = t >> 3, pseg = t & 7;   // psum mapping: 32 rows x 8 segments

    // ---- prologue: load slab 0 ----
    {
        #pragma unroll
        for (int i = 0; i < 4; ++i) {
            int idx = t + i * 256;
            int r = idx >> 5, c4 = idx & 31;
            cp16(smem_u32(xsb0 + r * 132 + c4 * 4), xp + (size_t)r * HW_ + c4 * 4);
        }
        #pragma unroll
        for (int i = 0; i < 2; ++i) {
            int idx = t + i * 256;
            int o = idx >> 3, kc = idx & 7;
            cp16(smem_u32(wtb0 + o * 36 + kc * 4), conv_w + o * C_ + kc * 4);
        }
        CP_COMMIT();
    }

    for (int slab = 0; slab < 8; ++slab) {
        int cur = slab & 1;
        float* xc = cur ? xsb1 : xsb0;
        float* wc = cur ? wtb1 : wtb0;
        if (slab < 7) {
            float* xn = cur ? xsb0 : xsb1;
            float* wnx = cur ? wtb0 : wtb1;
            int ns = slab + 1;
            #pragma unroll
            for (int i = 0; i < 4; ++i) {
                int idx = t + i * 256;
                int r = idx >> 5, c4 = idx & 31;
                cp16(smem_u32(xn + r * 132 + c4 * 4),
                     xp + (size_t)(ns * 32 + r) * HW_ + c4 * 4);
            }
            #pragma unroll
            for (int i = 0; i < 2; ++i) {
                int idx = t + i * 256;
                int o = idx >> 3, kc = idx & 7;
                cp16(smem_u32(wnx + o * 36 + kc * 4),
                     conv_w + o * C_ + ns * 32 + kc * 4);
            }
            CP_COMMIT();
            CP_WAIT(1);
        } else {
            CP_WAIT(0);
        }
        __syncthreads();

        // channel partial sums for the global mean (raw fp32, deterministic)
        {
            float s = 0.f;
            #pragma unroll
            for (int i = 0; i < 16; ++i) s += xc[prow * 132 + pseg * 16 + i];
            s += __shfl_down_sync(0xffffffffu, s, 4, 8);
            s += __shfl_down_sync(0xffffffffu, s, 2, 8);
            s += __shfl_down_sync(0xffffffffu, s, 1, 8);
            if (pseg == 0) psp[slab * 32 + prow] = s;
        }

        #pragma unroll
        for (int kk = 0; kk < 4; ++kk) {
            int k0 = kk * 8;
            uint32_t a[2][4];
            #pragma unroll
            for (int mt = 0; mt < 2; ++mt) {
                int px = wm * 32 + mt * 16 + gq;
                a[mt][0] = __float_as_uint(f2tf(xc[(k0 + gr) * 132 + px]));
                a[mt][1] = __float_as_uint(f2tf(xc[(k0 + gr) * 132 + px + 8]));
                a[mt][2] = __float_as_uint(f2tf(xc[(k0 + gr + 4) * 132 + px]));
                a[mt][3] = __float_as_uint(f2tf(xc[(k0 + gr + 4) * 132 + px + 8]));
            }
            #pragma unroll
            for (int nt = 0; nt < 4; ++nt) {
                int o = wn * 32 + nt * 8 + gq;
                uint32_t b0 = __float_as_uint(f2tf(wc[o * 36 + k0 + gr]));
                uint32_t b1 = __float_as_uint(f2tf(wc[o * 36 + k0 + gr + 4]));
                mma8(acc[0][nt], a[0], b0, b1);
                mma8(acc[1][nt], a[1], b0, b1);
            }
        }
        __syncthreads();
    }

    // ---- epilogue: stage per-warp 32px x 32out tile -> coalesced writes ----
    float* st = sm + warp * 1056;  // 32*33, overlays xs region (synced above)
    #pragma unroll
    for (int mt = 0; mt < 2; ++mt)
        #pragma unroll
        for (int nt = 0; nt < 4; ++nt) {
            int pr = mt * 16 + gq, oc = nt * 8 + 2 * gr;
            st[pr * 33 + oc]           = acc[mt][nt][0];
            st[pr * 33 + oc + 1]       = acc[mt][nt][1];
            st[(pr + 8) * 33 + oc]     = acc[mt][nt][2];
            st[(pr + 8) * 33 + oc + 1] = acc[mt][nt][3];
        }
    __syncwarp();
    float* fp = g_f + (size_t)n * CM_ * HW_ + base + wm * 32;
    #pragma unroll
    for (int ol = 0; ol < 32; ++ol) {
        int o = wn * 32 + ol;
        float v = st[lane * 33 + ol] + conv_b[o];
        fp[(size_t)o * HW_ + lane] = fmaxf(v, 0.f);
    }
}

// ---------------- kernel 2: finish mean + g + dynamic depthwise weights ----------------
__global__ __launch_bounds__(256) void weights_kernel(
    const float* __restrict__ conv_w, const float* __restrict__ conv_b,
    const float* __restrict__ ckw,  const float* __restrict__ ckb,
    const float* __restrict__ ck2w, const float* __restrict__ ck2b,
    const float* __restrict__ kw,   const float* __restrict__ kb,
    const float* __restrict__ k2w,  const float* __restrict__ k2b)
{
    __shared__ float sm[C_];
    int n = blockIdx.x;
    int t = threadIdx.x;
    {
        const float* pp = g_psum + (size_t)n * NBLK_ * C_ + t;
        float s = 0.f;
        #pragma unroll 8
        for (int b = 0; b < NBLK_; ++b) s += pp[(size_t)b * C_];
        sm[t] = s * (1.0f / (float)HW_);
    }
    __syncthreads();
    int warp = t >> 5, lane = t & 31;
    float a1 = ckw[0],  b1 = ckb[0];
    float a2 = ck2w[0], b2 = ck2b[0];
    for (int c = warp; c < CM_; c += 8) {
        float s = 0.f;
        #pragma unroll
        for (int kk = 0; kk < 8; kk++)
            s += sm[lane + kk * 32] * conv_w[c * C_ + lane + kk * 32];
        #pragma unroll
        for (int o = 16; o > 0; o >>= 1) s += __shfl_xor_sync(0xffffffffu, s, o);
        float g = fmaxf(s + conv_b[c], 0.f);
        int idx = n * CM_ + c;
        if (lane < 25) g_wdyn[idx * 25 + lane] = fmaf(a1, fmaf(g, kw[lane],  kb[lane]),  b1);
        if (lane < 9)  g_watr[idx * 9  + lane] = fmaf(a2, fmaf(g, k2w[lane], k2b[lane]), b2);
    }
}

// ---------------- kernel 3: both dynamic depthwise convs (register-tiled) ----------------
__global__ __launch_bounds__(256) void dw_kernel(
    const float* __restrict__ adap_b, const float* __restrict__ atrous_b)
{
    __shared__ float sf[36][100];
    __shared__ float w5[25], w3[9];
    int t  = threadIdx.x;
    int rc = blockIdx.x;   // 0..2 (32-row chunks)
    int c  = blockIdx.y;
    int n  = blockIdx.z;
    int r0 = rc * 32;
    const float* fp = g_f + ((size_t)n * CM_ + c) * HW_;

    for (int idx = t; idx < 3600; idx += 256) {
        int i = idx / 100, j = idx - i * 100;
        int grow = r0 - 2 + i, gcol = j - 2;
        float v = 0.f;
        if (grow >= 0 && grow < H_ && gcol >= 0 && gcol < W_) v = fp[grow * W_ + gcol];
        sf[i][j] = v;
    }
    if (t < 25) w5[t] = g_wdyn[((size_t)n * CM_ + c) * 25 + t];
    if (t < 9)  w3[t] = g_watr[((size_t)n * CM_ + c) * 9 + t];
    __syncthreads();

    float ab  = adap_b[c];
    float atb = atrous_b[c];
    float* o0 = g_dw0 + ((size_t)n * CM_ + c) * HW_;
    float* o1 = g_dw1 + ((size_t)n * CM_ + c) * HW_;

    #pragma unroll
    for (int q = 0; q < 3; ++q) {
        int task = t + q * 256;            // 0..767: 8 row-groups x 96 cols
        int rg = task / 96, cc = task - rg * 96;
        float s[8][5];
        #pragma unroll
        for (int i = 0; i < 8; ++i)
            #pragma unroll
            for (int j = 0; j < 5; ++j)
                s[i][j] = sf[rg * 4 + i][cc + j];

        float a5[4] = {ab, ab, ab, ab};
        #pragma unroll
        for (int rr = 0; rr < 4; ++rr)
            #pragma unroll
            for (int i = 0; i < 5; ++i)
                #pragma unroll
                for (int j = 0; j < 5; ++j)
                    a5[rr] = fmaf(w5[i * 5 + j], s[rr + i][j], a5[rr]);

        float a3[4] = {atb, atb, atb, atb};
        #pragma unroll
        for (int rr = 0; rr < 4; ++rr)
            #pragma unroll
            for (int i = 0; i < 3; ++i)
                #pragma unroll
                for (int j = 0; j < 3; ++j)
                    a3[rr] = fmaf(w3[i * 3 + j], s[rr + 2 * i][2 * j], a3[rr]);

        int rbase = r0 + rg * 4;
        #pragma unroll
        for (int rr = 0; rr < 4; ++rr) {
            o0[(rbase + rr) * W_ + cc] = a5[rr];
            o1[(rbase + rr) * W_ + cc] = a3[rr];
        }
    }
}

// ---------------- kernel 4: fuse GEMM via tf32 mma, cp.async double-buffered ----------------
// Block tile: 128 px x 128 outs, K=64 in 2 slabs of 32. Full fuse_w resident.
// smem (floats): xs[2][32][132] @0 (8448), wt[128][76] @8448 (9728)
__global__ __launch_bounds__(256) void fuse_mma(
    float* __restrict__ out,
    const float* __restrict__ fuse_w,
    const float* __restrict__ fuse_b)
{
    extern __shared__ float sm[];
    float* xsb0 = sm;
    float* xsb1 = sm + 4224;
    float* wt   = sm + 8448;

    int t = threadIdx.x, lane = t & 31, warp = t >> 5;
    int gq = lane >> 2, gr = lane & 3;
    int n = blockIdx.y, br = blockIdx.z;
    int base = blockIdx.x * 128;
    int wm = warp & 3, wn = warp >> 2;
    const float* dwp = (br ? g_dw1 : g_dw0) + (size_t)n * CM_ * HW_ + base;

    float acc[2][8][4];
    #pragma unroll
    for (int a = 0; a < 2; a++)
        #pragma unroll
        for (int b = 0; b < 8; b++)
            #pragma unroll
            for (int c = 0; c < 4; c++) acc[a][b][c] = 0.f;

    // ---- prologue: A slab 0 + full weights (group 0), A slab 1 (group 1) ----
    #pragma unroll
    for (int i = 0; i < 4; ++i) {
        int idx = t + i * 256;
        int r = idx >> 5, c4 = idx & 31;
        cp16(smem_u32(xsb0 + r * 132 + c4 * 4), dwp + (size_t)r * HW_ + c4 * 4);
    }
    #pragma unroll
    for (int i = 0; i < 8; ++i) {
        int idx = t + i * 256;
        int o = idx >> 4, kc = idx & 15;
        cp16(smem_u32(wt + o * 76 + kc * 4), fuse_w + o * 64 + kc * 4);
    }
    CP_COMMIT();
    #pragma unroll
    for (int i = 0; i < 4; ++i) {
        int idx = t + i * 256;
        int r = idx >> 5, c4 = idx & 31;
        cp16(smem_u32(xsb1 + r * 132 + c4 * 4), dwp + (size_t)(32 + r) * HW_ + c4 * 4);
    }
    CP_COMMIT();

    #pragma unroll
    for (int slab = 0; slab < 2; ++slab) {
        float* xc = slab ? xsb1 : xsb0;
        if (slab == 0) CP_WAIT(1); else CP_WAIT(0);
        __syncthreads();
        #pragma unroll
        for (int kk = 0; kk < 4; ++kk) {
            int k0 = kk * 8;
            int kg = slab * 32 + k0;
            uint32_t a[2][4];
            #pragma unroll
            for (int mt = 0; mt < 2; ++mt) {
                int px = wm * 32 + mt * 16 + gq;
                a[mt][0] = __float_as_uint(f2tf(xc[(k0 + gr) * 132 + px]));
                a[mt][1] = __float_as_uint(f2tf(xc[(k0 + gr) * 132 + px + 8]));
                a[mt][2] = __float_as_uint(f2tf(xc[(k0 + gr + 4) * 132 + px]));
                a[mt][3] = __float_as_uint(f2tf(xc[(k0 + gr + 4) * 132 + px + 8]));
            }
            #pragma unroll
            for (int nt = 0; nt < 8; ++nt) {
                int o = wn * 64 + nt * 8 + gq;
                uint32_t b0 = __float_as_uint(f2tf(wt[o * 76 + kg + gr]));
                uint32_t b1 = __float_as_uint(f2tf(wt[o * 76 + kg + gr + 4]));
                mma8(acc[0][nt], a[0], b0, b1);
                mma8(acc[1][nt], a[1], b0, b1);
            }
        }
        __syncthreads();
    }

    // ---- epilogue: two 32-out halves per warp through staging tile ----
    float* st = sm + warp * 1056;   // overlays xs region
    float* yp = out + ((size_t)n * 256 + (size_t)br * 128 + (size_t)wn * 64) * HW_ + base + wm * 32;
    #pragma unroll
    for (int h = 0; h < 2; ++h) {
        __syncwarp();
        #pragma unroll
        for (int mt = 0; mt < 2; ++mt)
            #pragma unroll
            for (int n4 = 0; n4 < 4; ++n4) {
                int nt = h * 4 + n4;
                int pr = mt * 16 + gq, oc = n4 * 8 + 2 * gr;
                st[pr * 33 + oc]           = acc[mt][nt][0];
                st[pr * 33 + oc + 1]       = acc[mt][nt][1];
                st[(pr + 8) * 33 + oc]     = acc[mt][nt][2];
                st[(pr + 8) * 33 + oc + 1] = acc[mt][nt][3];
            }
        __syncwarp();
        #pragma unroll
        for (int ol = 0; ol < 32; ++ol) {
            int og = h * 32 + ol;
            float v = st[lane * 33 + ol] + fuse_b[wn * 64 + og];
            yp[(size_t)og * HW_ + lane] = v;
        }
    }
}

// ---------------- launcher ----------------
#define CONV1_SMEM ((8448 + 4608) * 4)
#define FUSE_SMEM  ((8448 + 9728) * 4)

extern "C" void kernel_launch(void* const* d_in, const int* in_sizes, int n_in,
                              void* d_out, int out_size) {
    const float* x        = (const float*)d_in[0];
    const float* conv_w   = (const float*)d_in[1];
    const float* conv_b   = (const float*)d_in[2];
    const float* ckw      = (const float*)d_in[3];
    const float* ckb      = (const float*)d_in[4];
    const float* ck2w     = (const float*)d_in[5];
    const float* ck2b     = (const float*)d_in[6];
    const float* kw       = (const float*)d_in[7];
    const float* kb       = (const float*)d_in[8];
    const float* k2w      = (const float*)d_in[9];
    const float* k2b      = (const float*)d_in[10];
    const float* fuse_w   = (const float*)d_in[11];
    const float* fuse_b   = (const float*)d_in[12];
    const float* adap_b   = (const float*)d_in[13];
    const float* atrous_b = (const float*)d_in[14];
    float* out = (float*)d_out;

    cudaFuncSetAttribute(conv1_mma, cudaFuncAttributeMaxDynamicSharedMemorySize, CONV1_SMEM);
    cudaFuncSetAttribute(fuse_mma,  cudaFuncAttributeMaxDynamicSharedMemorySize, FUSE_SMEM);

    conv1_mma<<<dim3(NBLK_, N_), 256, CONV1_SMEM>>>(x, conv_w, conv_b);
    weights_kernel<<<N_, 256>>>(conv_w, conv_b, ckw, ckb, ck2w, ck2b, kw, kb, k2w, k2b);
    dw_kernel<<<dim3(3, CM_, N_), 256>>>(adap_b, atrous_b);
    fuse_mma<<<dim3(HW_ / 128, N_, 2), 256, FUSE_SMEM>>>(out, fuse_w, fuse_b);
}